// round 7
// baseline (speedup 1.0000x reference)
#include <cuda_runtime.h>

// Problem shapes (fixed by the dataset)
#define BSZ  8
#define ENL  512   // encoder length
#define DEL  64    // decoder length
#define EDIM 512   // embedding
#define UDIM 512   // units
#define TDIM 100   // topics
#define STRIP 16   // strip depth in fused kernel

// Scratch (no cudaMalloc allowed)
__device__ float g_aeT[BSZ * UDIM * ENL];   // att_en transposed: [b][u][i]  (8 MB)
__device__ float g_c  [BSZ * DEL * UDIM];   // att_de + topic bias: [b][j][u] (1 MB)

typedef unsigned long long ull;

__device__ __forceinline__ float tanh_fast(float x) {
    float y;
    asm("tanh.approx.f32 %0, %1;" : "=f"(y) : "f"(x));
    return y;
}
__device__ __forceinline__ ull pack2(float x, float y) {
    ull r; asm("mov.b64 %0, {%1, %2};" : "=l"(r) : "f"(x), "f"(y)); return r;
}
__device__ __forceinline__ void unpack2(ull p, float& x, float& y) {
    asm("mov.b64 {%0, %1}, %2;" : "=f"(x), "=f"(y) : "l"(p));
}
__device__ __forceinline__ ull fma2(ull a, ull b, ull c) {
    ull d; asm("fma.rn.f32x2 %0, %1, %2, %3;" : "=l"(d) : "l"(a), "l"(b), "l"(c));
    return d;
}

// ---------------------------------------------------------------------------
// Kernel 1: g_aeT[b][u][i] = sum_e en[b][i][e] * w_en[e][u]
// 64(i) x 128(u) tile, BK=16, 256 threads, 8(u)x4(i) microtile.
// B (the i operand) is stored DUPLICATED in smem as (v,v) pairs, so the inner
// loop needs zero pack movs: 4x LDS.128 + 16x FFMA2 per k-step.
// acc[i][up] = f32x2 accumulator over a u-pair for column i.
// ---------------------------------------------------------------------------
__global__ void __launch_bounds__(256, 2) k_gemm_aeT(
    const float* __restrict__ en, const float* __restrict__ w_en)
{
    const int b  = blockIdx.z;
    const int u0 = blockIdx.y * 128;
    const int i0 = blockIdx.x * 64;

    __shared__ float As [2][16][128];  // [e][u] plain
    __shared__ float Bs2[2][16][132];  // [e][2*i] duplicated pairs (row 528B, 16B-mult)

    const int tid = threadIdx.x;
    const int tx = tid & 15;          // i micro index (4 i's)
    const int ty = tid >> 4;          // u micro index (8 u's = 4 pairs)

    const int ua = tid & 127;
    const int ea = tid >> 7;
    const int eb = tid & 15;
    const int ib = tid >> 4;

    const float* pa = w_en + (size_t)ea * UDIM + u0 + ua;
    const float* pb = en + (size_t)b * ENL * EDIM + (size_t)(i0 + ib) * EDIM + eb;

    ull acc[4][4] = {};   // [i][u-pair]

    // Prologue: tile 0
    #pragma unroll
    for (int p = 0; p < 8; p++)
        As[0][ea + 2 * p][ua] = pa[(size_t)(2 * p) * UDIM];
    #pragma unroll
    for (int p = 0; p < 4; p++) {
        float v = pb[(size_t)(16 * p) * EDIM];
        *(ull*)&Bs2[0][eb][2 * (ib + 16 * p)] = pack2(v, v);
    }
    __syncthreads();

    int s = 0;
    for (int t = 0; t < 32; t++) {
        float ra[8], rb[4];
        if (t < 31) {
            const float* qa = pa + (size_t)(t + 1) * 16 * UDIM;
            const float* qb = pb + (t + 1) * 16;
            #pragma unroll
            for (int p = 0; p < 8; p++) ra[p] = qa[(size_t)(2 * p) * UDIM];
            #pragma unroll
            for (int p = 0; p < 4; p++) rb[p] = qb[(size_t)(16 * p) * EDIM];
        }
        #pragma unroll
        for (int k = 0; k < 16; k++) {
            const ulonglong2 A01 = *(const ulonglong2*)&As[s][k][ty * 8];
            const ulonglong2 A23 = *(const ulonglong2*)&As[s][k][ty * 8 + 4];
            const ulonglong2 B01 = *(const ulonglong2*)&Bs2[s][k][tx * 8];
            const ulonglong2 B23 = *(const ulonglong2*)&Bs2[s][k][tx * 8 + 4];
            acc[0][0]=fma2(A01.x,B01.x,acc[0][0]); acc[0][1]=fma2(A01.y,B01.x,acc[0][1]);
            acc[0][2]=fma2(A23.x,B01.x,acc[0][2]); acc[0][3]=fma2(A23.y,B01.x,acc[0][3]);
            acc[1][0]=fma2(A01.x,B01.y,acc[1][0]); acc[1][1]=fma2(A01.y,B01.y,acc[1][1]);
            acc[1][2]=fma2(A23.x,B01.y,acc[1][2]); acc[1][3]=fma2(A23.y,B01.y,acc[1][3]);
            acc[2][0]=fma2(A01.x,B23.x,acc[2][0]); acc[2][1]=fma2(A01.y,B23.x,acc[2][1]);
            acc[2][2]=fma2(A23.x,B23.x,acc[2][2]); acc[2][3]=fma2(A23.y,B23.x,acc[2][3]);
            acc[3][0]=fma2(A01.x,B23.y,acc[3][0]); acc[3][1]=fma2(A01.y,B23.y,acc[3][1]);
            acc[3][2]=fma2(A23.x,B23.y,acc[3][2]); acc[3][3]=fma2(A23.y,B23.y,acc[3][3]);
        }
        if (t < 31) {
            #pragma unroll
            for (int p = 0; p < 8; p++) As[s ^ 1][ea + 2 * p][ua] = ra[p];
            #pragma unroll
            for (int p = 0; p < 4; p++)
                *(ull*)&Bs2[s ^ 1][eb][2 * (ib + 16 * p)] = pack2(rb[p], rb[p]);
        }
        __syncthreads();
        s ^= 1;
    }

    // Epilogue: acc[i][up] -> rows of g_aeT[u][i]
    float f[4][8];   // [i][u_local]
    #pragma unroll
    for (int i = 0; i < 4; i++)
        #pragma unroll
        for (int up = 0; up < 4; up++)
            unpack2(acc[i][up], f[i][2 * up], f[i][2 * up + 1]);

    float* outp = g_aeT + (size_t)b * UDIM * ENL
                + (size_t)(u0 + ty * 8) * ENL + i0 + tx * 4;
    #pragma unroll
    for (int q = 0; q < 8; q++) {
        float4 v = make_float4(f[0][q], f[1][q], f[2][q], f[3][q]);
        *(float4*)(outp + (size_t)q * ENL) = v;
    }
}

// ---------------------------------------------------------------------------
// Kernel 2: g_c[b][j][u] = sum_e de[b][j][e] * w_de[e][u] + tw[b][u]
// ---------------------------------------------------------------------------
__global__ void __launch_bounds__(256) k_c(
    const float* __restrict__ de, const float* __restrict__ w_de,
    const float* __restrict__ topics, const float* __restrict__ wt)
{
    const int b  = blockIdx.y;
    const int u0 = blockIdx.x * 64;
    __shared__ float As[16][68];  // [e][j]
    __shared__ float Bs[16][68];  // [e][u]
    __shared__ float tws[64];
    const float* deb = de + (size_t)b * DEL * EDIM;
    const int tid = threadIdx.x;
    const int tj = tid & 15;
    const int tu = tid >> 4;
    ull acc2[4][2] = {};

    if (tid < 64) {
        float acc = 0.f;
        const float* wr = wt + (size_t)(u0 + tid) * TDIM;
        const float* tp = topics + b * TDIM;
        #pragma unroll 4
        for (int t = 0; t < TDIM; t++) acc = fmaf(tp[t], wr[t], acc);
        tws[tid] = acc;
    }

    for (int e0 = 0; e0 < EDIM; e0 += 16) {
        #pragma unroll
        for (int r = 0; r < 4; r++) {
            int l = tid + 256 * r;
            int e = l & 15, j = l >> 4;
            As[e][j] = deb[(size_t)j * EDIM + e0 + e];
        }
        #pragma unroll
        for (int r = 0; r < 4; r++) {
            int l = tid + 256 * r;
            int e = l >> 6, uu = l & 63;
            Bs[e][uu] = w_de[(size_t)(e0 + e) * UDIM + u0 + uu];
        }
        __syncthreads();
        #pragma unroll
        for (int k = 0; k < 16; k++) {
            const float4 av = *(const float4*)&As[k][tj * 4];
            const ull b01 = *(const ull*)&Bs[k][tu * 4];
            const ull b23 = *(const ull*)&Bs[k][tu * 4 + 2];
            ull pa0 = pack2(av.x, av.x), pa1 = pack2(av.y, av.y);
            ull pa2 = pack2(av.z, av.z), pa3 = pack2(av.w, av.w);
            acc2[0][0] = fma2(pa0, b01, acc2[0][0]); acc2[0][1] = fma2(pa0, b23, acc2[0][1]);
            acc2[1][0] = fma2(pa1, b01, acc2[1][0]); acc2[1][1] = fma2(pa1, b23, acc2[1][1]);
            acc2[2][0] = fma2(pa2, b01, acc2[2][0]); acc2[2][1] = fma2(pa2, b23, acc2[2][1]);
            acc2[3][0] = fma2(pa3, b01, acc2[3][0]); acc2[3][1] = fma2(pa3, b23, acc2[3][1]);
        }
        __syncthreads();
    }
    #pragma unroll
    for (int r = 0; r < 4; r++) {
        float2 v01, v23;
        unpack2(acc2[r][0], v01.x, v01.y);
        unpack2(acc2[r][1], v23.x, v23.y);
        int j = tj * 4 + r;
        float* row = g_c + ((size_t)b * DEL + j) * UDIM + u0 + tu * 4;
        row[0] = v01.x + tws[tu * 4 + 0];
        row[1] = v01.y + tws[tu * 4 + 1];
        row[2] = v23.x + tws[tu * 4 + 2];
        row[3] = v23.y + tws[tu * 4 + 3];
    }
}

// ---------------------------------------------------------------------------
// Kernel 3 (fused attention): block = (b, j0..j0+3), 512 threads, JT=4,
// register double-buffered strips. grid = 16 x 8 = 128 blocks.
// ---------------------------------------------------------------------------
__global__ void __launch_bounds__(512) k_attn(
    const float* __restrict__ en, const float* __restrict__ de,
    const float* __restrict__ nu, float* __restrict__ out)
{
    const int b  = blockIdx.y;
    const int j0 = blockIdx.x * 4;
    const int t  = threadIdx.x;

    __shared__ float4 css[UDIM];   // (c[j0..j0+3][u])
    __shared__ float  nus[UDIM];
    __shared__ float4 red4[16];
    __shared__ float4 alph[ENL];

    const float* cb = g_c + ((size_t)b * DEL + j0) * UDIM;
    css[t] = make_float4(cb[t], cb[UDIM + t], cb[2 * UDIM + t], cb[3 * UDIM + t]);
    nus[t] = nu[t];
    __syncthreads();

    // Phase 1: mu for i = t, 4 j's. Software-pipelined strips of 16.
    const float* ae = g_aeT + (size_t)b * UDIM * ENL + t;
    float m0 = 0.f, m1 = 0.f, m2 = 0.f, m3 = 0.f;
    {
        float bufA[STRIP], bufB[STRIP];
        #pragma unroll
        for (int k = 0; k < STRIP; k++)
            bufA[k] = __ldg(ae + (size_t)k * ENL);

        #pragma unroll 1
        for (int u0 = 0; u0 < UDIM; u0 += 2 * STRIP) {
            #pragma unroll
            for (int k = 0; k < STRIP; k++)
                bufB[k] = __ldg(ae + (size_t)(u0 + STRIP + k) * ENL);
            #pragma unroll
            for (int k = 0; k < STRIP; k++) {
                float4 c4 = css[u0 + k];
                float nv = nus[u0 + k];
                m0 = fmaf(nv, tanh_fast(bufA[k] + c4.x), m0);
                m1 = fmaf(nv, tanh_fast(bufA[k] + c4.y), m1);
                m2 = fmaf(nv, tanh_fast(bufA[k] + c4.z), m2);
                m3 = fmaf(nv, tanh_fast(bufA[k] + c4.w), m3);
            }
            if (u0 + 2 * STRIP < UDIM) {
                #pragma unroll
                for (int k = 0; k < STRIP; k++)
                    bufA[k] = __ldg(ae + (size_t)(u0 + 2 * STRIP + k) * ENL);
            }
            #pragma unroll
            for (int k = 0; k < STRIP; k++) {
                float4 c4 = css[u0 + STRIP + k];
                float nv = nus[u0 + STRIP + k];
                m0 = fmaf(nv, tanh_fast(bufB[k] + c4.x), m0);
                m1 = fmaf(nv, tanh_fast(bufB[k] + c4.y), m1);
                m2 = fmaf(nv, tanh_fast(bufB[k] + c4.z), m2);
                m3 = fmaf(nv, tanh_fast(bufB[k] + c4.w), m3);
            }
        }
    }

    const int wid = t >> 5, lane = t & 31;

    // Block max (4 j's at once)
    float4 r = make_float4(m0, m1, m2, m3);
    #pragma unroll
    for (int o = 16; o; o >>= 1) {
        r.x = fmaxf(r.x, __shfl_xor_sync(0xffffffffu, r.x, o));
        r.y = fmaxf(r.y, __shfl_xor_sync(0xffffffffu, r.y, o));
        r.z = fmaxf(r.z, __shfl_xor_sync(0xffffffffu, r.z, o));
        r.w = fmaxf(r.w, __shfl_xor_sync(0xffffffffu, r.w, o));
    }
    if (lane == 0) red4[wid] = r;
    __syncthreads();
    float4 M = red4[0];
    #pragma unroll
    for (int w = 1; w < 16; w++) {
        float4 q = red4[w];
        M.x = fmaxf(M.x, q.x); M.y = fmaxf(M.y, q.y);
        M.z = fmaxf(M.z, q.z); M.w = fmaxf(M.w, q.w);
    }
    __syncthreads();  // before reusing red4

    float e0 = __expf(m0 - M.x);
    float e1 = __expf(m1 - M.y);
    float e2 = __expf(m2 - M.z);
    float e3 = __expf(m3 - M.w);

    // Block sum
    float4 s = make_float4(e0, e1, e2, e3);
    #pragma unroll
    for (int o = 16; o; o >>= 1) {
        s.x += __shfl_xor_sync(0xffffffffu, s.x, o);
        s.y += __shfl_xor_sync(0xffffffffu, s.y, o);
        s.z += __shfl_xor_sync(0xffffffffu, s.z, o);
        s.w += __shfl_xor_sync(0xffffffffu, s.w, o);
    }
    if (lane == 0) red4[wid] = s;
    __syncthreads();
    float4 S = red4[0];
    #pragma unroll
    for (int w = 1; w < 16; w++) {
        float4 q = red4[w];
        S.x += q.x; S.y += q.y; S.z += q.z; S.w += q.w;
    }

    float a0 = e0 / S.x, a1 = e1 / S.y, a2 = e2 / S.z, a3 = e3 / S.w;
    alph[t] = make_float4(a0, a1, a2, a3);

    // Output layout (flat tuple): [output | alphas | p_gen]
    float* alphas_out = out + BSZ * DEL * ENL;
    float* pgen_out   = out + 2 * BSZ * DEL * ENL;
    const int base = ((b * DEL + j0) * ENL) + t;
    alphas_out[base          ] = a0;
    alphas_out[base +     ENL] = a1;
    alphas_out[base + 2 * ENL] = a2;
    alphas_out[base + 3 * ENL] = a3;
    pgen_out[base          ] = 1.f / (1.f + __expf(-m0));
    pgen_out[base +     ENL] = 1.f / (1.f + __expf(-m1));
    pgen_out[base + 2 * ENL] = 1.f / (1.f + __expf(-m2));
    pgen_out[base + 3 * ENL] = 1.f / (1.f + __expf(-m3));
    __syncthreads();

    // Phase 2: sum_en[j][e=t] = sum_i alphas[j][i] * en[b][i][e], pipelined.
    float s0 = 0.f, s1 = 0.f, s2 = 0.f, s3 = 0.f;
    const float* enb = en + (size_t)b * ENL * EDIM + t;
    {
        float bufA[STRIP], bufB[STRIP];
        #pragma unroll
        for (int k = 0; k < STRIP; k++)
            bufA[k] = __ldg(enb + (size_t)k * EDIM);

        #pragma unroll 1
        for (int i0 = 0; i0 < ENL; i0 += 2 * STRIP) {
            #pragma unroll
            for (int k = 0; k < STRIP; k++)
                bufB[k] = __ldg(enb + (size_t)(i0 + STRIP + k) * EDIM);
            #pragma unroll
            for (int k = 0; k < STRIP; k++) {
                float4 av = alph[i0 + k];
                s0 = fmaf(av.x, bufA[k], s0);
                s1 = fmaf(av.y, bufA[k], s1);
                s2 = fmaf(av.z, bufA[k], s2);
                s3 = fmaf(av.w, bufA[k], s3);
            }
            if (i0 + 2 * STRIP < ENL) {
                #pragma unroll
                for (int k = 0; k < STRIP; k++)
                    bufA[k] = __ldg(enb + (size_t)(i0 + 2 * STRIP + k) * EDIM);
            }
            #pragma unroll
            for (int k = 0; k < STRIP; k++) {
                float4 av = alph[i0 + STRIP + k];
                s0 = fmaf(av.x, bufB[k], s0);
                s1 = fmaf(av.y, bufB[k], s1);
                s2 = fmaf(av.z, bufB[k], s2);
                s3 = fmaf(av.w, bufB[k], s3);
            }
        }
    }
    const int ob = ((b * DEL + j0) * EDIM) + t;
    out[ob           ] = de[ob           ] + s0;
    out[ob +     EDIM] = de[ob +     EDIM] + s1;
    out[ob + 2 * EDIM] = de[ob + 2 * EDIM] + s2;
    out[ob + 3 * EDIM] = de[ob + 3 * EDIM] + s3;
}

// ---------------------------------------------------------------------------
extern "C" void kernel_launch(void* const* d_in, const int* in_sizes, int n_in,
                              void* d_out, int out_size)
{
    const float* en     = (const float*)d_in[0];
    const float* de     = (const float*)d_in[1];
    const float* topics = (const float*)d_in[2];
    const float* w_en   = (const float*)d_in[3];
    const float* w_de   = (const float*)d_in[4];
    const float* nu     = (const float*)d_in[5];
    const float* wt     = (const float*)d_in[6];
    float* out = (float*)d_out;

    k_gemm_aeT<<<dim3(ENL / 64, UDIM / 128, BSZ), 256>>>(en, w_en);
    k_c<<<dim3(UDIM / 64, BSZ), 256>>>(de, w_de, topics, wt);
    k_attn<<<dim3(DEL / 4, BSZ), 512>>>(en, de, nu, out);
}

// round 8
// speedup vs baseline: 1.2562x; 1.2562x over previous
#include <cuda_runtime.h>

// Problem shapes (fixed by the dataset)
#define BSZ  8
#define ENL  512   // encoder length
#define DEL  64    // decoder length
#define EDIM 512   // embedding
#define UDIM 512   // units
#define TDIM 100   // topics
#define STRIP 16   // strip depth in fused kernel

// Scratch (no cudaMalloc allowed)
__device__ float g_aeT[BSZ * UDIM * ENL];   // att_en transposed: [b][u][i]  (8 MB)
__device__ float g_c  [BSZ * DEL * UDIM];   // att_de + topic bias: [b][j][u] (1 MB)

typedef unsigned long long ull;

__device__ __forceinline__ float tanh_fast(float x) {
    float y;
    asm("tanh.approx.f32 %0, %1;" : "=f"(y) : "f"(x));
    return y;
}
__device__ __forceinline__ ull pack2(float x, float y) {
    ull r; asm("mov.b64 %0, {%1, %2};" : "=l"(r) : "f"(x), "f"(y)); return r;
}
__device__ __forceinline__ void unpack2(ull p, float& x, float& y) {
    asm("mov.b64 {%0, %1}, %2;" : "=f"(x), "=f"(y) : "l"(p));
}
__device__ __forceinline__ ull fma2(ull a, ull b, ull c) {
    ull d; asm("fma.rn.f32x2 %0, %1, %2, %3;" : "=l"(d) : "l"(a), "l"(b), "l"(c));
    return d;
}

// ---------------------------------------------------------------------------
// Kernel 1: g_aeT[b][u][i] = sum_e en[b][i][e] * w_en[e][u]
// 64(i) x 128(u) tile, BK=16, 256 threads, 8(u)x4(i) microtile.
// A (the u operand) is stored DUPLICATED in smem as (a,a) pairs. A reads are
// warp-broadcast (all tx lanes share one ty), so duplication is conflict-free.
// B stays natural: one LDS.128 yields two native (b0,b1)/(b2,b3) ull pairs.
// Inner loop: 4x LDS.128(bcast) + 1x LDS.128 + 16x FFMA2 — zero pack movs.
// acc[u][ip]: f32x2 accumulator over an i-pair for row u.
// ---------------------------------------------------------------------------
__global__ void __launch_bounds__(256, 2) k_gemm_aeT(
    const float* __restrict__ en, const float* __restrict__ w_en)
{
    const int b  = blockIdx.z;
    const int u0 = blockIdx.y * 128;
    const int i0 = blockIdx.x * 64;

    __shared__ float As2[2][16][256];  // [e][2*u] duplicated (a,a) pairs
    __shared__ float Bs [2][16][68];   // [e][i] natural (padded)

    const int tid = threadIdx.x;
    const int tx = tid & 15;          // i micro index (4 i's)
    const int ty = tid >> 4;          // u micro index (8 u's)

    const int ua = tid & 127;
    const int ea = tid >> 7;
    const int eb = tid & 15;
    const int ib = tid >> 4;

    const float* pa = w_en + (size_t)ea * UDIM + u0 + ua;
    const float* pb = en + (size_t)b * ENL * EDIM + (size_t)(i0 + ib) * EDIM + eb;

    ull acc[8][2] = {};   // [u][i-pair]

    // Prologue: tile 0
    #pragma unroll
    for (int p = 0; p < 8; p++) {
        float v = pa[(size_t)(2 * p) * UDIM];
        *(ull*)&As2[0][ea + 2 * p][2 * ua] = pack2(v, v);
    }
    #pragma unroll
    for (int p = 0; p < 4; p++)
        Bs[0][eb][ib + 16 * p] = pb[(size_t)(16 * p) * EDIM];
    __syncthreads();

    int s = 0;
    for (int t = 0; t < 32; t++) {
        float ra[8], rb[4];
        if (t < 31) {
            const float* qa = pa + (size_t)(t + 1) * 16 * UDIM;
            const float* qb = pb + (t + 1) * 16;
            #pragma unroll
            for (int p = 0; p < 8; p++) ra[p] = qa[(size_t)(2 * p) * UDIM];
            #pragma unroll
            for (int p = 0; p < 4; p++) rb[p] = qb[(size_t)(16 * p) * EDIM];
        }
        #pragma unroll
        for (int k = 0; k < 16; k++) {
            // A-dup: 8 u's = 8 (a,a) pairs = 4x 16B broadcast loads
            const ulonglong2 A01 = *(const ulonglong2*)&As2[s][k][ty * 16];
            const ulonglong2 A23 = *(const ulonglong2*)&As2[s][k][ty * 16 + 4];
            const ulonglong2 A45 = *(const ulonglong2*)&As2[s][k][ty * 16 + 8];
            const ulonglong2 A67 = *(const ulonglong2*)&As2[s][k][ty * 16 + 12];
            // B natural: float4 -> two native i-pairs
            const ulonglong2 B = *(const ulonglong2*)&Bs[s][k][tx * 4];
            acc[0][0]=fma2(A01.x,B.x,acc[0][0]); acc[0][1]=fma2(A01.x,B.y,acc[0][1]);
            acc[1][0]=fma2(A01.y,B.x,acc[1][0]); acc[1][1]=fma2(A01.y,B.y,acc[1][1]);
            acc[2][0]=fma2(A23.x,B.x,acc[2][0]); acc[2][1]=fma2(A23.x,B.y,acc[2][1]);
            acc[3][0]=fma2(A23.y,B.x,acc[3][0]); acc[3][1]=fma2(A23.y,B.y,acc[3][1]);
            acc[4][0]=fma2(A45.x,B.x,acc[4][0]); acc[4][1]=fma2(A45.x,B.y,acc[4][1]);
            acc[5][0]=fma2(A45.y,B.x,acc[5][0]); acc[5][1]=fma2(A45.y,B.y,acc[5][1]);
            acc[6][0]=fma2(A67.x,B.x,acc[6][0]); acc[6][1]=fma2(A67.x,B.y,acc[6][1]);
            acc[7][0]=fma2(A67.y,B.x,acc[7][0]); acc[7][1]=fma2(A67.y,B.y,acc[7][1]);
        }
        if (t < 31) {
            #pragma unroll
            for (int p = 0; p < 8; p++)
                *(ull*)&As2[s ^ 1][ea + 2 * p][2 * ua] = pack2(ra[p], ra[p]);
            #pragma unroll
            for (int p = 0; p < 4; p++) Bs[s ^ 1][eb][ib + 16 * p] = rb[p];
        }
        __syncthreads();
        s ^= 1;
    }

    // Epilogue: acc[u][ip] holds (out[u][2ip], out[u][2ip+1]) — contiguous in i.
    float* outp = g_aeT + (size_t)b * UDIM * ENL
                + (size_t)(u0 + ty * 8) * ENL + i0 + tx * 4;
    #pragma unroll
    for (int q = 0; q < 8; q++) {
        ull* row = (ull*)(outp + (size_t)q * ENL);
        row[0] = acc[q][0]; row[1] = acc[q][1];
    }
}

// ---------------------------------------------------------------------------
// Kernel 2: g_c[b][j][u] = sum_e de[b][j][e] * w_de[e][u] + tw[b][u]
// ---------------------------------------------------------------------------
__global__ void __launch_bounds__(256) k_c(
    const float* __restrict__ de, const float* __restrict__ w_de,
    const float* __restrict__ topics, const float* __restrict__ wt)
{
    const int b  = blockIdx.y;
    const int u0 = blockIdx.x * 64;
    __shared__ float As[16][68];  // [e][j]
    __shared__ float Bs[16][68];  // [e][u]
    __shared__ float tws[64];
    const float* deb = de + (size_t)b * DEL * EDIM;
    const int tid = threadIdx.x;
    const int tj = tid & 15;
    const int tu = tid >> 4;
    ull acc2[4][2] = {};

    if (tid < 64) {
        float acc = 0.f;
        const float* wr = wt + (size_t)(u0 + tid) * TDIM;
        const float* tp = topics + b * TDIM;
        #pragma unroll 4
        for (int t = 0; t < TDIM; t++) acc = fmaf(tp[t], wr[t], acc);
        tws[tid] = acc;
    }

    for (int e0 = 0; e0 < EDIM; e0 += 16) {
        #pragma unroll
        for (int r = 0; r < 4; r++) {
            int l = tid + 256 * r;
            int e = l & 15, j = l >> 4;
            As[e][j] = deb[(size_t)j * EDIM + e0 + e];
        }
        #pragma unroll
        for (int r = 0; r < 4; r++) {
            int l = tid + 256 * r;
            int e = l >> 6, uu = l & 63;
            Bs[e][uu] = w_de[(size_t)(e0 + e) * UDIM + u0 + uu];
        }
        __syncthreads();
        #pragma unroll
        for (int k = 0; k < 16; k++) {
            const float4 av = *(const float4*)&As[k][tj * 4];
            const ull b01 = *(const ull*)&Bs[k][tu * 4];
            const ull b23 = *(const ull*)&Bs[k][tu * 4 + 2];
            ull pa0 = pack2(av.x, av.x), pa1 = pack2(av.y, av.y);
            ull pa2 = pack2(av.z, av.z), pa3 = pack2(av.w, av.w);
            acc2[0][0] = fma2(pa0, b01, acc2[0][0]); acc2[0][1] = fma2(pa0, b23, acc2[0][1]);
            acc2[1][0] = fma2(pa1, b01, acc2[1][0]); acc2[1][1] = fma2(pa1, b23, acc2[1][1]);
            acc2[2][0] = fma2(pa2, b01, acc2[2][0]); acc2[2][1] = fma2(pa2, b23, acc2[2][1]);
            acc2[3][0] = fma2(pa3, b01, acc2[3][0]); acc2[3][1] = fma2(pa3, b23, acc2[3][1]);
        }
        __syncthreads();
    }
    #pragma unroll
    for (int r = 0; r < 4; r++) {
        float2 v01, v23;
        unpack2(acc2[r][0], v01.x, v01.y);
        unpack2(acc2[r][1], v23.x, v23.y);
        int j = tj * 4 + r;
        float* row = g_c + ((size_t)b * DEL + j) * UDIM + u0 + tu * 4;
        row[0] = v01.x + tws[tu * 4 + 0];
        row[1] = v01.y + tws[tu * 4 + 1];
        row[2] = v23.x + tws[tu * 4 + 2];
        row[3] = v23.y + tws[tu * 4 + 3];
    }
}

// ---------------------------------------------------------------------------
// Kernel 3 (fused attention): block = (b, j0..j0+1), 512 threads,
// register double-buffered strips (R6 configuration — measured best).
// ---------------------------------------------------------------------------
__global__ void __launch_bounds__(512) k_attn(
    const float* __restrict__ en, const float* __restrict__ de,
    const float* __restrict__ nu, float* __restrict__ out)
{
    const int b  = blockIdx.y;
    const int j0 = blockIdx.x * 2;
    const int t  = threadIdx.x;

    __shared__ float4 css[UDIM];   // (c[j0][u], c[j0+1][u], nu[u], 0)
    __shared__ float2 red2[16];
    __shared__ float2 alph[ENL];

    const float* cb = g_c + ((size_t)b * DEL + j0) * UDIM;
    css[t] = make_float4(cb[t], cb[UDIM + t], nu[t], 0.f);
    __syncthreads();

    // Phase 1: mu for i = t, 2 j's. Software-pipelined strips.
    const float* ae = g_aeT + (size_t)b * UDIM * ENL + t;
    float m0 = 0.f, m1 = 0.f;
    {
        float bufA[STRIP], bufB[STRIP];
        #pragma unroll
        for (int k = 0; k < STRIP; k++)
            bufA[k] = __ldg(ae + (size_t)k * ENL);

        #pragma unroll 1
        for (int u0 = 0; u0 < UDIM; u0 += 2 * STRIP) {
            #pragma unroll
            for (int k = 0; k < STRIP; k++)
                bufB[k] = __ldg(ae + (size_t)(u0 + STRIP + k) * ENL);
            #pragma unroll
            for (int k = 0; k < STRIP; k++) {
                float4 c4 = css[u0 + k];
                m0 = fmaf(c4.z, tanh_fast(bufA[k] + c4.x), m0);
                m1 = fmaf(c4.z, tanh_fast(bufA[k] + c4.y), m1);
            }
            if (u0 + 2 * STRIP < UDIM) {
                #pragma unroll
                for (int k = 0; k < STRIP; k++)
                    bufA[k] = __ldg(ae + (size_t)(u0 + 2 * STRIP + k) * ENL);
            }
            #pragma unroll
            for (int k = 0; k < STRIP; k++) {
                float4 c4 = css[u0 + STRIP + k];
                m0 = fmaf(c4.z, tanh_fast(bufB[k] + c4.x), m0);
                m1 = fmaf(c4.z, tanh_fast(bufB[k] + c4.y), m1);
            }
        }
    }

    const int wid = t >> 5, lane = t & 31;

    float2 r = make_float2(m0, m1);
    #pragma unroll
    for (int o = 16; o; o >>= 1) {
        r.x = fmaxf(r.x, __shfl_xor_sync(0xffffffffu, r.x, o));
        r.y = fmaxf(r.y, __shfl_xor_sync(0xffffffffu, r.y, o));
    }
    if (lane == 0) red2[wid] = r;
    __syncthreads();
    float2 M = red2[0];
    #pragma unroll
    for (int w = 1; w < 16; w++) {
        float2 q = red2[w];
        M.x = fmaxf(M.x, q.x); M.y = fmaxf(M.y, q.y);
    }
    __syncthreads();

    float e0 = __expf(m0 - M.x);
    float e1 = __expf(m1 - M.y);

    float2 s = make_float2(e0, e1);
    #pragma unroll
    for (int o = 16; o; o >>= 1) {
        s.x += __shfl_xor_sync(0xffffffffu, s.x, o);
        s.y += __shfl_xor_sync(0xffffffffu, s.y, o);
    }
    if (lane == 0) red2[wid] = s;
    __syncthreads();
    float2 S = red2[0];
    #pragma unroll
    for (int w = 1; w < 16; w++) {
        float2 q = red2[w];
        S.x += q.x; S.y += q.y;
    }

    float a0 = e0 / S.x, a1 = e1 / S.y;
    alph[t] = make_float2(a0, a1);

    float* alphas_out = out + BSZ * DEL * ENL;
    float* pgen_out   = out + 2 * BSZ * DEL * ENL;
    const int base = ((b * DEL + j0) * ENL) + t;
    alphas_out[base      ] = a0;
    alphas_out[base + ENL] = a1;
    pgen_out[base      ] = 1.f / (1.f + __expf(-m0));
    pgen_out[base + ENL] = 1.f / (1.f + __expf(-m1));
    __syncthreads();

    // Phase 2: sum_en[j][e=t] = sum_i alphas[j][i] * en[b][i][e], pipelined.
    float s0 = 0.f, s1 = 0.f;
    const float* enb = en + (size_t)b * ENL * EDIM + t;
    {
        float bufA[STRIP], bufB[STRIP];
        #pragma unroll
        for (int k = 0; k < STRIP; k++)
            bufA[k] = __ldg(enb + (size_t)k * EDIM);

        #pragma unroll 1
        for (int i0 = 0; i0 < ENL; i0 += 2 * STRIP) {
            #pragma unroll
            for (int k = 0; k < STRIP; k++)
                bufB[k] = __ldg(enb + (size_t)(i0 + STRIP + k) * EDIM);
            #pragma unroll
            for (int k = 0; k < STRIP; k++) {
                float2 av = alph[i0 + k];
                s0 = fmaf(av.x, bufA[k], s0);
                s1 = fmaf(av.y, bufA[k], s1);
            }
            if (i0 + 2 * STRIP < ENL) {
                #pragma unroll
                for (int k = 0; k < STRIP; k++)
                    bufA[k] = __ldg(enb + (size_t)(i0 + 2 * STRIP + k) * EDIM);
            }
            #pragma unroll
            for (int k = 0; k < STRIP; k++) {
                float2 av = alph[i0 + STRIP + k];
                s0 = fmaf(av.x, bufB[k], s0);
                s1 = fmaf(av.y, bufB[k], s1);
            }
        }
    }
    const int ob = ((b * DEL + j0) * EDIM) + t;
    out[ob       ] = de[ob       ] + s0;
    out[ob + EDIM] = de[ob + EDIM] + s1;
}

// ---------------------------------------------------------------------------
extern "C" void kernel_launch(void* const* d_in, const int* in_sizes, int n_in,
                              void* d_out, int out_size)
{
    const float* en     = (const float*)d_in[0];
    const float* de     = (const float*)d_in[1];
    const float* topics = (const float*)d_in[2];
    const float* w_en   = (const float*)d_in[3];
    const float* w_de   = (const float*)d_in[4];
    const float* nu     = (const float*)d_in[5];
    const float* wt     = (const float*)d_in[6];
    float* out = (float*)d_out;

    k_gemm_aeT<<<dim3(ENL / 64, UDIM / 128, BSZ), 256>>>(en, w_en);
    k_c<<<dim3(UDIM / 64, BSZ), 256>>>(de, w_de, topics, wt);
    k_attn<<<dim3(DEL / 2, BSZ), 512>>>(en, de, nu, out);
}

// round 9
// speedup vs baseline: 1.3669x; 1.0882x over previous
#include <cuda_runtime.h>
#include <cuda_fp16.h>

// Problem shapes (fixed by the dataset)
#define BSZ  8
#define ENL  512   // encoder length
#define DEL  64    // decoder length
#define EDIM 512   // embedding
#define UDIM 512   // units
#define TDIM 100   // topics
#define STRIP 16   // strip depth in fused kernel

// Scratch (no cudaMalloc allowed)
__device__ float g_aeT[BSZ * UDIM * ENL];   // att_en transposed: [b][u][i]  (8 MB)
__device__ float g_c  [BSZ * DEL * UDIM];   // att_de + topic bias: [b][j][u] (1 MB)

typedef unsigned long long ull;

__device__ __forceinline__ ull pack2(float x, float y) {
    ull r; asm("mov.b64 %0, {%1, %2};" : "=l"(r) : "f"(x), "f"(y)); return r;
}
__device__ __forceinline__ void unpack2(ull p, float& x, float& y) {
    asm("mov.b64 {%0, %1}, %2;" : "=f"(x), "=f"(y) : "l"(p));
}
__device__ __forceinline__ ull fma2(ull a, ull b, ull c) {
    ull d; asm("fma.rn.f32x2 %0, %1, %2, %3;" : "=l"(d) : "l"(a), "l"(b), "l"(c));
    return d;
}
// Two tanhs in one MUFU op: returns (tanh(s0), tanh(s1)) in fp32.
__device__ __forceinline__ float2 tanh2_f16(float s0, float s1) {
    unsigned p, q;
    asm("cvt.rn.f16x2.f32 %0, %1, %2;" : "=r"(p) : "f"(s1), "f"(s0)); // lo=s0, hi=s1
    asm("tanh.approx.f16x2 %0, %1;" : "=r"(q) : "r"(p));
    __half2 h = *reinterpret_cast<__half2*>(&q);
    return __half22float2(h);   // (lo, hi)
}

// ---------------------------------------------------------------------------
// Kernel 1: g_aeT[b][u][i] = sum_e en[b][i][e] * w_en[e][u]
// 64(i) x 128(u) tile, BK=16, 256 threads, 8(u)x4(i) microtile.
// A read as NATIVE f32 pairs (u-pairs) — zero movs. B splatted with 4 movs.
// Inner loop: 2x LDS.128(A, warp-broadcast) + 1x LDS.128(B) + 4 movs + 16 FFMA2.
// acc[up][i]: f32x2 accumulator over u-pair 'up' for column i.
// ---------------------------------------------------------------------------
__global__ void __launch_bounds__(256, 2) k_gemm_aeT(
    const float* __restrict__ en, const float* __restrict__ w_en)
{
    const int b  = blockIdx.z;
    const int u0 = blockIdx.y * 128;
    const int i0 = blockIdx.x * 64;

    __shared__ float As[2][16][128];  // [e][u]
    __shared__ float Bs[2][16][68];   // [e][i] (padded)

    const int tid = threadIdx.x;
    const int tx = tid & 15;          // i micro index (4 i's)
    const int ty = tid >> 4;          // u micro index (8 u's = 4 pairs)

    const int ua = tid & 127;
    const int ea = tid >> 7;
    const int eb = tid & 15;
    const int ib = tid >> 4;

    const float* pa = w_en + (size_t)ea * UDIM + u0 + ua;
    const float* pb = en + (size_t)b * ENL * EDIM + (size_t)(i0 + ib) * EDIM + eb;

    ull acc[4][4] = {};   // [u-pair][i]

    #pragma unroll
    for (int p = 0; p < 8; p++)
        As[0][ea + 2 * p][ua] = pa[(size_t)(2 * p) * UDIM];
    #pragma unroll
    for (int p = 0; p < 4; p++)
        Bs[0][eb][ib + 16 * p] = pb[(size_t)(16 * p) * EDIM];
    __syncthreads();

    int s = 0;
    for (int t = 0; t < 32; t++) {
        float ra[8], rb[4];
        if (t < 31) {
            const float* qa = pa + (size_t)(t + 1) * 16 * UDIM;
            const float* qb = pb + (t + 1) * 16;
            #pragma unroll
            for (int p = 0; p < 8; p++) ra[p] = qa[(size_t)(2 * p) * UDIM];
            #pragma unroll
            for (int p = 0; p < 4; p++) rb[p] = qb[(size_t)(16 * p) * EDIM];
        }
        #pragma unroll
        for (int k = 0; k < 16; k++) {
            // A native u-pairs: (a0,a1),(a2,a3),(a4,a5),(a6,a7)
            const ulonglong2 A03 = *(const ulonglong2*)&As[s][k][ty * 8];
            const ulonglong2 A47 = *(const ulonglong2*)&As[s][k][ty * 8 + 4];
            // B: 4 i values, splat each (4 movs)
            const float4 bv = *(const float4*)&Bs[s][k][tx * 4];
            const ull b0 = pack2(bv.x, bv.x), b1 = pack2(bv.y, bv.y);
            const ull b2 = pack2(bv.z, bv.z), b3 = pack2(bv.w, bv.w);
            acc[0][0]=fma2(A03.x,b0,acc[0][0]); acc[0][1]=fma2(A03.x,b1,acc[0][1]);
            acc[0][2]=fma2(A03.x,b2,acc[0][2]); acc[0][3]=fma2(A03.x,b3,acc[0][3]);
            acc[1][0]=fma2(A03.y,b0,acc[1][0]); acc[1][1]=fma2(A03.y,b1,acc[1][1]);
            acc[1][2]=fma2(A03.y,b2,acc[1][2]); acc[1][3]=fma2(A03.y,b3,acc[1][3]);
            acc[2][0]=fma2(A47.x,b0,acc[2][0]); acc[2][1]=fma2(A47.x,b1,acc[2][1]);
            acc[2][2]=fma2(A47.x,b2,acc[2][2]); acc[2][3]=fma2(A47.x,b3,acc[2][3]);
            acc[3][0]=fma2(A47.y,b0,acc[3][0]); acc[3][1]=fma2(A47.y,b1,acc[3][1]);
            acc[3][2]=fma2(A47.y,b2,acc[3][2]); acc[3][3]=fma2(A47.y,b3,acc[3][3]);
        }
        if (t < 31) {
            #pragma unroll
            for (int p = 0; p < 8; p++) As[s ^ 1][ea + 2 * p][ua] = ra[p];
            #pragma unroll
            for (int p = 0; p < 4; p++) Bs[s ^ 1][eb][ib + 16 * p] = rb[p];
        }
        __syncthreads();
        s ^= 1;
    }

    // Epilogue: acc[up][i] = (out[2up][i], out[2up+1][i])
    float f[8][4];
    #pragma unroll
    for (int up = 0; up < 4; up++)
        #pragma unroll
        for (int i = 0; i < 4; i++)
            unpack2(acc[up][i], f[2 * up][i], f[2 * up + 1][i]);

    float* outp = g_aeT + (size_t)b * UDIM * ENL
                + (size_t)(u0 + ty * 8) * ENL + i0 + tx * 4;
    #pragma unroll
    for (int q = 0; q < 8; q++)
        *(float4*)(outp + (size_t)q * ENL) = make_float4(f[q][0], f[q][1], f[q][2], f[q][3]);
}

// ---------------------------------------------------------------------------
// Kernel 2: g_c[b][j][u] = sum_e de[b][j][e] * w_de[e][u] + tw[b][u]
// ---------------------------------------------------------------------------
__global__ void __launch_bounds__(256) k_c(
    const float* __restrict__ de, const float* __restrict__ w_de,
    const float* __restrict__ topics, const float* __restrict__ wt)
{
    const int b  = blockIdx.y;
    const int u0 = blockIdx.x * 64;
    __shared__ float As[16][68];  // [e][j]
    __shared__ float Bs[16][68];  // [e][u]
    __shared__ float tws[64];
    const float* deb = de + (size_t)b * DEL * EDIM;
    const int tid = threadIdx.x;
    const int tj = tid & 15;
    const int tu = tid >> 4;
    ull acc2[4][2] = {};

    if (tid < 64) {
        float acc = 0.f;
        const float* wr = wt + (size_t)(u0 + tid) * TDIM;
        const float* tp = topics + b * TDIM;
        #pragma unroll 4
        for (int t = 0; t < TDIM; t++) acc = fmaf(tp[t], wr[t], acc);
        tws[tid] = acc;
    }

    for (int e0 = 0; e0 < EDIM; e0 += 16) {
        #pragma unroll
        for (int r = 0; r < 4; r++) {
            int l = tid + 256 * r;
            int e = l & 15, j = l >> 4;
            As[e][j] = deb[(size_t)j * EDIM + e0 + e];
        }
        #pragma unroll
        for (int r = 0; r < 4; r++) {
            int l = tid + 256 * r;
            int e = l >> 6, uu = l & 63;
            Bs[e][uu] = w_de[(size_t)(e0 + e) * UDIM + u0 + uu];
        }
        __syncthreads();
        #pragma unroll
        for (int k = 0; k < 16; k++) {
            const float4 av = *(const float4*)&As[k][tj * 4];
            const ull b01 = *(const ull*)&Bs[k][tu * 4];
            const ull b23 = *(const ull*)&Bs[k][tu * 4 + 2];
            ull pa0 = pack2(av.x, av.x), pa1 = pack2(av.y, av.y);
            ull pa2 = pack2(av.z, av.z), pa3 = pack2(av.w, av.w);
            acc2[0][0] = fma2(pa0, b01, acc2[0][0]); acc2[0][1] = fma2(pa0, b23, acc2[0][1]);
            acc2[1][0] = fma2(pa1, b01, acc2[1][0]); acc2[1][1] = fma2(pa1, b23, acc2[1][1]);
            acc2[2][0] = fma2(pa2, b01, acc2[2][0]); acc2[2][1] = fma2(pa2, b23, acc2[2][1]);
            acc2[3][0] = fma2(pa3, b01, acc2[3][0]); acc2[3][1] = fma2(pa3, b23, acc2[3][1]);
        }
        __syncthreads();
    }
    #pragma unroll
    for (int r = 0; r < 4; r++) {
        float2 v01, v23;
        unpack2(acc2[r][0], v01.x, v01.y);
        unpack2(acc2[r][1], v23.x, v23.y);
        int j = tj * 4 + r;
        float* row = g_c + ((size_t)b * DEL + j) * UDIM + u0 + tu * 4;
        row[0] = v01.x + tws[tu * 4 + 0];
        row[1] = v01.y + tws[tu * 4 + 1];
        row[2] = v23.x + tws[tu * 4 + 2];
        row[3] = v23.y + tws[tu * 4 + 3];
    }
}

// ---------------------------------------------------------------------------
// Kernel 3 (fused attention): block = (b, j0..j0+1), 512 threads,
// f16x2 tanh (2 tanhs / MUFU op), register double-buffered strips.
// ---------------------------------------------------------------------------
__global__ void __launch_bounds__(512) k_attn(
    const float* __restrict__ en, const float* __restrict__ de,
    const float* __restrict__ nu, float* __restrict__ out)
{
    const int b  = blockIdx.y;
    const int j0 = blockIdx.x * 2;
    const int t  = threadIdx.x;

    __shared__ float4 css[UDIM];   // (c[j0][u], c[j0+1][u], nu[u], 0)
    __shared__ float2 red2[16];
    __shared__ float2 alph[ENL];

    const float* cb = g_c + ((size_t)b * DEL + j0) * UDIM;
    css[t] = make_float4(cb[t], cb[UDIM + t], nu[t], 0.f);
    __syncthreads();

    // Phase 1: mu for i = t, 2 j's. One tanh.approx.f16x2 per u.
    const float* ae = g_aeT + (size_t)b * UDIM * ENL + t;
    float m0 = 0.f, m1 = 0.f;
    {
        float bufA[STRIP], bufB[STRIP];
        #pragma unroll
        for (int k = 0; k < STRIP; k++)
            bufA[k] = __ldg(ae + (size_t)k * ENL);

        #pragma unroll 1
        for (int u0 = 0; u0 < UDIM; u0 += 2 * STRIP) {
            #pragma unroll
            for (int k = 0; k < STRIP; k++)
                bufB[k] = __ldg(ae + (size_t)(u0 + STRIP + k) * ENL);
            #pragma unroll
            for (int k = 0; k < STRIP; k++) {
                float4 c4 = css[u0 + k];
                float2 th = tanh2_f16(bufA[k] + c4.x, bufA[k] + c4.y);
                m0 = fmaf(c4.z, th.x, m0);
                m1 = fmaf(c4.z, th.y, m1);
            }
            if (u0 + 2 * STRIP < UDIM) {
                #pragma unroll
                for (int k = 0; k < STRIP; k++)
                    bufA[k] = __ldg(ae + (size_t)(u0 + 2 * STRIP + k) * ENL);
            }
            #pragma unroll
            for (int k = 0; k < STRIP; k++) {
                float4 c4 = css[u0 + STRIP + k];
                float2 th = tanh2_f16(bufB[k] + c4.x, bufB[k] + c4.y);
                m0 = fmaf(c4.z, th.x, m0);
                m1 = fmaf(c4.z, th.y, m1);
            }
        }
    }

    const int wid = t >> 5, lane = t & 31;

    float2 r = make_float2(m0, m1);
    #pragma unroll
    for (int o = 16; o; o >>= 1) {
        r.x = fmaxf(r.x, __shfl_xor_sync(0xffffffffu, r.x, o));
        r.y = fmaxf(r.y, __shfl_xor_sync(0xffffffffu, r.y, o));
    }
    if (lane == 0) red2[wid] = r;
    __syncthreads();
    float2 M = red2[0];
    #pragma unroll
    for (int w = 1; w < 16; w++) {
        float2 q = red2[w];
        M.x = fmaxf(M.x, q.x); M.y = fmaxf(M.y, q.y);
    }
    __syncthreads();

    float e0 = __expf(m0 - M.x);
    float e1 = __expf(m1 - M.y);

    float2 s = make_float2(e0, e1);
    #pragma unroll
    for (int o = 16; o; o >>= 1) {
        s.x += __shfl_xor_sync(0xffffffffu, s.x, o);
        s.y += __shfl_xor_sync(0xffffffffu, s.y, o);
    }
    if (lane == 0) red2[wid] = s;
    __syncthreads();
    float2 S = red2[0];
    #pragma unroll
    for (int w = 1; w < 16; w++) {
        float2 q = red2[w];
        S.x += q.x; S.y += q.y;
    }

    float a0 = e0 / S.x, a1 = e1 / S.y;
    alph[t] = make_float2(a0, a1);

    float* alphas_out = out + BSZ * DEL * ENL;
    float* pgen_out   = out + 2 * BSZ * DEL * ENL;
    const int base = ((b * DEL + j0) * ENL) + t;
    alphas_out[base      ] = a0;
    alphas_out[base + ENL] = a1;
    pgen_out[base      ] = 1.f / (1.f + __expf(-m0));
    pgen_out[base + ENL] = 1.f / (1.f + __expf(-m1));
    __syncthreads();

    // Phase 2: sum_en[j][e=t] = sum_i alphas[j][i] * en[b][i][e], pipelined.
    float s0 = 0.f, s1 = 0.f;
    const float* enb = en + (size_t)b * ENL * EDIM + t;
    {
        float bufA[STRIP], bufB[STRIP];
        #pragma unroll
        for (int k = 0; k < STRIP; k++)
            bufA[k] = __ldg(enb + (size_t)k * EDIM);

        #pragma unroll 1
        for (int i0 = 0; i0 < ENL; i0 += 2 * STRIP) {
            #pragma unroll
            for (int k = 0; k < STRIP; k++)
                bufB[k] = __ldg(enb + (size_t)(i0 + STRIP + k) * EDIM);
            #pragma unroll
            for (int k = 0; k < STRIP; k++) {
                float2 av = alph[i0 + k];
                s0 = fmaf(av.x, bufA[k], s0);
                s1 = fmaf(av.y, bufA[k], s1);
            }
            if (i0 + 2 * STRIP < ENL) {
                #pragma unroll
                for (int k = 0; k < STRIP; k++)
                    bufA[k] = __ldg(enb + (size_t)(i0 + 2 * STRIP + k) * EDIM);
            }
            #pragma unroll
            for (int k = 0; k < STRIP; k++) {
                float2 av = alph[i0 + STRIP + k];
                s0 = fmaf(av.x, bufB[k], s0);
                s1 = fmaf(av.y, bufB[k], s1);
            }
        }
    }
    const int ob = ((b * DEL + j0) * EDIM) + t;
    out[ob       ] = de[ob       ] + s0;
    out[ob + EDIM] = de[ob + EDIM] + s1;
}

// ---------------------------------------------------------------------------
extern "C" void kernel_launch(void* const* d_in, const int* in_sizes, int n_in,
                              void* d_out, int out_size)
{
    const float* en     = (const float*)d_in[0];
    const float* de     = (const float*)d_in[1];
    const float* topics = (const float*)d_in[2];
    const float* w_en   = (const float*)d_in[3];
    const float* w_de   = (const float*)d_in[4];
    const float* nu     = (const float*)d_in[5];
    const float* wt     = (const float*)d_in[6];
    float* out = (float*)d_out;

    k_gemm_aeT<<<dim3(ENL / 64, UDIM / 128, BSZ), 256>>>(en, w_en);
    k_c<<<dim3(UDIM / 64, BSZ), 256>>>(de, w_de, topics, wt);
    k_attn<<<dim3(DEL / 2, BSZ), 512>>>(en, de, nu, out);
}

// round 10
// speedup vs baseline: 1.4079x; 1.0300x over previous
#include <cuda_runtime.h>
#include <cuda_fp16.h>

// Problem shapes (fixed by the dataset)
#define BSZ  8
#define ENL  512   // encoder length
#define DEL  64    // decoder length
#define EDIM 512   // embedding
#define UDIM 512   // units
#define TDIM 100   // topics
#define STRIP 8    // strip depth in fused kernel (regs tight at 1024 thr)

// Scratch (no cudaMalloc allowed)
__device__ float g_aeT[BSZ * UDIM * ENL];   // att_en transposed: [b][u][i]  (8 MB)
__device__ float g_c  [BSZ * DEL * UDIM];   // att_de + topic bias: [b][j][u] (1 MB)

typedef unsigned long long ull;

__device__ __forceinline__ ull pack2(float x, float y) {
    ull r; asm("mov.b64 %0, {%1, %2};" : "=l"(r) : "f"(x), "f"(y)); return r;
}
__device__ __forceinline__ void unpack2(ull p, float& x, float& y) {
    asm("mov.b64 {%0, %1}, %2;" : "=f"(x), "=f"(y) : "l"(p));
}
__device__ __forceinline__ ull fma2(ull a, ull b, ull c) {
    ull d; asm("fma.rn.f32x2 %0, %1, %2, %3;" : "=l"(d) : "l"(a), "l"(b), "l"(c));
    return d;
}
// Two tanhs in one MUFU op: returns (tanh(s0), tanh(s1)) in fp32.
__device__ __forceinline__ float2 tanh2_f16(float s0, float s1) {
    unsigned p, q;
    asm("cvt.rn.f16x2.f32 %0, %1, %2;" : "=r"(p) : "f"(s1), "f"(s0)); // lo=s0, hi=s1
    asm("tanh.approx.f16x2 %0, %1;" : "=r"(q) : "r"(p));
    __half2 h = *reinterpret_cast<__half2*>(&q);
    return __half22float2(h);   // (lo, hi)
}

// ---------------------------------------------------------------------------
// Kernel 1: g_aeT[b][u][i] = sum_e en[b][i][e] * w_en[e][u]
// 64(i) x 128(u) tile, BK=16, 256 threads, 8(u)x4(i) microtile.
// A read as NATIVE f32 pairs — zero movs. B splatted with 4 movs per k-step.
// ---------------------------------------------------------------------------
__global__ void __launch_bounds__(256, 2) k_gemm_aeT(
    const float* __restrict__ en, const float* __restrict__ w_en)
{
    const int b  = blockIdx.z;
    const int u0 = blockIdx.y * 128;
    const int i0 = blockIdx.x * 64;

    __shared__ float As[2][16][128];  // [e][u]
    __shared__ float Bs[2][16][68];   // [e][i] (padded)

    const int tid = threadIdx.x;
    const int tx = tid & 15;
    const int ty = tid >> 4;

    const int ua = tid & 127;
    const int ea = tid >> 7;
    const int eb = tid & 15;
    const int ib = tid >> 4;

    const float* pa = w_en + (size_t)ea * UDIM + u0 + ua;
    const float* pb = en + (size_t)b * ENL * EDIM + (size_t)(i0 + ib) * EDIM + eb;

    ull acc[4][4] = {};   // [u-pair][i]

    #pragma unroll
    for (int p = 0; p < 8; p++)
        As[0][ea + 2 * p][ua] = pa[(size_t)(2 * p) * UDIM];
    #pragma unroll
    for (int p = 0; p < 4; p++)
        Bs[0][eb][ib + 16 * p] = pb[(size_t)(16 * p) * EDIM];
    __syncthreads();

    int s = 0;
    for (int t = 0; t < 32; t++) {
        float ra[8], rb[4];
        if (t < 31) {
            const float* qa = pa + (size_t)(t + 1) * 16 * UDIM;
            const float* qb = pb + (t + 1) * 16;
            #pragma unroll
            for (int p = 0; p < 8; p++) ra[p] = qa[(size_t)(2 * p) * UDIM];
            #pragma unroll
            for (int p = 0; p < 4; p++) rb[p] = qb[(size_t)(16 * p) * EDIM];
        }
        #pragma unroll
        for (int k = 0; k < 16; k++) {
            const ulonglong2 A03 = *(const ulonglong2*)&As[s][k][ty * 8];
            const ulonglong2 A47 = *(const ulonglong2*)&As[s][k][ty * 8 + 4];
            const float4 bv = *(const float4*)&Bs[s][k][tx * 4];
            const ull b0 = pack2(bv.x, bv.x), b1 = pack2(bv.y, bv.y);
            const ull b2 = pack2(bv.z, bv.z), b3 = pack2(bv.w, bv.w);
            acc[0][0]=fma2(A03.x,b0,acc[0][0]); acc[0][1]=fma2(A03.x,b1,acc[0][1]);
            acc[0][2]=fma2(A03.x,b2,acc[0][2]); acc[0][3]=fma2(A03.x,b3,acc[0][3]);
            acc[1][0]=fma2(A03.y,b0,acc[1][0]); acc[1][1]=fma2(A03.y,b1,acc[1][1]);
            acc[1][2]=fma2(A03.y,b2,acc[1][2]); acc[1][3]=fma2(A03.y,b3,acc[1][3]);
            acc[2][0]=fma2(A47.x,b0,acc[2][0]); acc[2][1]=fma2(A47.x,b1,acc[2][1]);
            acc[2][2]=fma2(A47.x,b2,acc[2][2]); acc[2][3]=fma2(A47.x,b3,acc[2][3]);
            acc[3][0]=fma2(A47.y,b0,acc[3][0]); acc[3][1]=fma2(A47.y,b1,acc[3][1]);
            acc[3][2]=fma2(A47.y,b2,acc[3][2]); acc[3][3]=fma2(A47.y,b3,acc[3][3]);
        }
        if (t < 31) {
            #pragma unroll
            for (int p = 0; p < 8; p++) As[s ^ 1][ea + 2 * p][ua] = ra[p];
            #pragma unroll
            for (int p = 0; p < 4; p++) Bs[s ^ 1][eb][ib + 16 * p] = rb[p];
        }
        __syncthreads();
        s ^= 1;
    }

    float f[8][4];
    #pragma unroll
    for (int up = 0; up < 4; up++)
        #pragma unroll
        for (int i = 0; i < 4; i++)
            unpack2(acc[up][i], f[2 * up][i], f[2 * up + 1][i]);

    float* outp = g_aeT + (size_t)b * UDIM * ENL
                + (size_t)(u0 + ty * 8) * ENL + i0 + tx * 4;
    #pragma unroll
    for (int q = 0; q < 8; q++)
        *(float4*)(outp + (size_t)q * ENL) = make_float4(f[q][0], f[q][1], f[q][2], f[q][3]);
}

// ---------------------------------------------------------------------------
// Kernel 2: g_c[b][j][u] = sum_e de[b][j][e] * w_de[e][u] + tw[b][u]
// ---------------------------------------------------------------------------
__global__ void __launch_bounds__(256) k_c(
    const float* __restrict__ de, const float* __restrict__ w_de,
    const float* __restrict__ topics, const float* __restrict__ wt)
{
    const int b  = blockIdx.y;
    const int u0 = blockIdx.x * 64;
    __shared__ float As[16][68];
    __shared__ float Bs[16][68];
    __shared__ float tws[64];
    const float* deb = de + (size_t)b * DEL * EDIM;
    const int tid = threadIdx.x;
    const int tj = tid & 15;
    const int tu = tid >> 4;
    ull acc2[4][2] = {};

    if (tid < 64) {
        float acc = 0.f;
        const float* wr = wt + (size_t)(u0 + tid) * TDIM;
        const float* tp = topics + b * TDIM;
        #pragma unroll 4
        for (int t = 0; t < TDIM; t++) acc = fmaf(tp[t], wr[t], acc);
        tws[tid] = acc;
    }

    for (int e0 = 0; e0 < EDIM; e0 += 16) {
        #pragma unroll
        for (int r = 0; r < 4; r++) {
            int l = tid + 256 * r;
            int e = l & 15, j = l >> 4;
            As[e][j] = deb[(size_t)j * EDIM + e0 + e];
        }
        #pragma unroll
        for (int r = 0; r < 4; r++) {
            int l = tid + 256 * r;
            int e = l >> 6, uu = l & 63;
            Bs[e][uu] = w_de[(size_t)(e0 + e) * UDIM + u0 + uu];
        }
        __syncthreads();
        #pragma unroll
        for (int k = 0; k < 16; k++) {
            const float4 av = *(const float4*)&As[k][tj * 4];
            const ull b01 = *(const ull*)&Bs[k][tu * 4];
            const ull b23 = *(const ull*)&Bs[k][tu * 4 + 2];
            ull pa0 = pack2(av.x, av.x), pa1 = pack2(av.y, av.y);
            ull pa2 = pack2(av.z, av.z), pa3 = pack2(av.w, av.w);
            acc2[0][0] = fma2(pa0, b01, acc2[0][0]); acc2[0][1] = fma2(pa0, b23, acc2[0][1]);
            acc2[1][0] = fma2(pa1, b01, acc2[1][0]); acc2[1][1] = fma2(pa1, b23, acc2[1][1]);
            acc2[2][0] = fma2(pa2, b01, acc2[2][0]); acc2[2][1] = fma2(pa2, b23, acc2[2][1]);
            acc2[3][0] = fma2(pa3, b01, acc2[3][0]); acc2[3][1] = fma2(pa3, b23, acc2[3][1]);
        }
        __syncthreads();
    }
    #pragma unroll
    for (int r = 0; r < 4; r++) {
        float2 v01, v23;
        unpack2(acc2[r][0], v01.x, v01.y);
        unpack2(acc2[r][1], v23.x, v23.y);
        int j = tj * 4 + r;
        float* row = g_c + ((size_t)b * DEL + j) * UDIM + u0 + tu * 4;
        row[0] = v01.x + tws[tu * 4 + 0];
        row[1] = v01.y + tws[tu * 4 + 1];
        row[2] = v23.x + tws[tu * 4 + 2];
        row[3] = v23.y + tws[tu * 4 + 3];
    }
}

// ---------------------------------------------------------------------------
// Kernel 3 (fused attention): block = (b, j0..j0+3), 1024 threads.
// Two 512-thread halves, each owns a j-pair; both halves read the same
// ae/en lines (2nd half hits L1) -> L2 traffic halves vs JT=2.
// grid = 16 x 8 = 128 blocks, 32 warps/SM.
// ---------------------------------------------------------------------------
__global__ void __launch_bounds__(1024, 1) k_attn(
    const float* __restrict__ en, const float* __restrict__ de,
    const float* __restrict__ nu, float* __restrict__ out)
{
    const int b    = blockIdx.y;
    const int j0   = blockIdx.x * 4;
    const int tid  = threadIdx.x;
    const int half = tid >> 9;          // 0 or 1 -> j-pair
    const int t    = tid & 511;         // i (phase 1) / e (phase 2)

    __shared__ float4 css[2][UDIM];     // [half][u] = (c[jA][u], c[jB][u], nu[u], 0)
    __shared__ float2 red2[2][16];
    __shared__ float2 alph[2][ENL];     // [half][i] = (alpha_jA, alpha_jB)

    const float* cb = g_c + ((size_t)b * DEL + j0 + 2 * half) * UDIM;
    css[half][t] = make_float4(cb[t], cb[UDIM + t], nu[t], 0.f);
    __syncthreads();

    // Phase 1: mu for i = t, own j-pair. Software-pipelined strips of 8.
    const float* ae = g_aeT + (size_t)b * UDIM * ENL + t;
    float m0 = 0.f, m1 = 0.f;
    {
        float bufA[STRIP], bufB[STRIP];
        #pragma unroll
        for (int k = 0; k < STRIP; k++)
            bufA[k] = __ldg(ae + (size_t)k * ENL);

        #pragma unroll 1
        for (int u0 = 0; u0 < UDIM; u0 += 2 * STRIP) {
            #pragma unroll
            for (int k = 0; k < STRIP; k++)
                bufB[k] = __ldg(ae + (size_t)(u0 + STRIP + k) * ENL);
            #pragma unroll
            for (int k = 0; k < STRIP; k++) {
                float4 c4 = css[half][u0 + k];
                float2 th = tanh2_f16(bufA[k] + c4.x, bufA[k] + c4.y);
                m0 = fmaf(c4.z, th.x, m0);
                m1 = fmaf(c4.z, th.y, m1);
            }
            if (u0 + 2 * STRIP < UDIM) {
                #pragma unroll
                for (int k = 0; k < STRIP; k++)
                    bufA[k] = __ldg(ae + (size_t)(u0 + 2 * STRIP + k) * ENL);
            }
            #pragma unroll
            for (int k = 0; k < STRIP; k++) {
                float4 c4 = css[half][u0 + STRIP + k];
                float2 th = tanh2_f16(bufB[k] + c4.x, bufB[k] + c4.y);
                m0 = fmaf(c4.z, th.x, m0);
                m1 = fmaf(c4.z, th.y, m1);
            }
        }
    }

    const int widl = t >> 5, lane = t & 31;

    // Per-half max over i
    float2 r = make_float2(m0, m1);
    #pragma unroll
    for (int o = 16; o; o >>= 1) {
        r.x = fmaxf(r.x, __shfl_xor_sync(0xffffffffu, r.x, o));
        r.y = fmaxf(r.y, __shfl_xor_sync(0xffffffffu, r.y, o));
    }
    if (lane == 0) red2[half][widl] = r;
    __syncthreads();
    float2 M = red2[half][0];
    #pragma unroll
    for (int w = 1; w < 16; w++) {
        float2 q = red2[half][w];
        M.x = fmaxf(M.x, q.x); M.y = fmaxf(M.y, q.y);
    }
    __syncthreads();  // before reusing red2

    float e0 = __expf(m0 - M.x);
    float e1 = __expf(m1 - M.y);

    // Per-half sum over i
    float2 s = make_float2(e0, e1);
    #pragma unroll
    for (int o = 16; o; o >>= 1) {
        s.x += __shfl_xor_sync(0xffffffffu, s.x, o);
        s.y += __shfl_xor_sync(0xffffffffu, s.y, o);
    }
    if (lane == 0) red2[half][widl] = s;
    __syncthreads();
    float2 S = red2[half][0];
    #pragma unroll
    for (int w = 1; w < 16; w++) {
        float2 q = red2[half][w];
        S.x += q.x; S.y += q.y;
    }

    float a0 = e0 / S.x, a1 = e1 / S.y;
    alph[half][t] = make_float2(a0, a1);

    // Output layout (flat tuple): [output | alphas | p_gen]
    float* alphas_out = out + BSZ * DEL * ENL;
    float* pgen_out   = out + 2 * BSZ * DEL * ENL;
    const int base = ((b * DEL + j0 + 2 * half) * ENL) + t;
    alphas_out[base      ] = a0;
    alphas_out[base + ENL] = a1;
    pgen_out[base      ] = 1.f / (1.f + __expf(-m0));
    pgen_out[base + ENL] = 1.f / (1.f + __expf(-m1));
    __syncthreads();

    // Phase 2: sum_en[j][e=t] = sum_i alphas[j][i] * en[b][i][e], pipelined.
    float s0 = 0.f, s1 = 0.f;
    const float* enb = en + (size_t)b * ENL * EDIM + t;
    {
        float bufA[STRIP], bufB[STRIP];
        #pragma unroll
        for (int k = 0; k < STRIP; k++)
            bufA[k] = __ldg(enb + (size_t)k * EDIM);

        #pragma unroll 1
        for (int i0 = 0; i0 < ENL; i0 += 2 * STRIP) {
            #pragma unroll
            for (int k = 0; k < STRIP; k++)
                bufB[k] = __ldg(enb + (size_t)(i0 + STRIP + k) * EDIM);
            #pragma unroll
            for (int k = 0; k < STRIP; k++) {
                float2 av = alph[half][i0 + k];
                s0 = fmaf(av.x, bufA[k], s0);
                s1 = fmaf(av.y, bufA[k], s1);
            }
            if (i0 + 2 * STRIP < ENL) {
                #pragma unroll
                for (int k = 0; k < STRIP; k++)
                    bufA[k] = __ldg(enb + (size_t)(i0 + 2 * STRIP + k) * EDIM);
            }
            #pragma unroll
            for (int k = 0; k < STRIP; k++) {
                float2 av = alph[half][i0 + STRIP + k];
                s0 = fmaf(av.x, bufB[k], s0);
                s1 = fmaf(av.y, bufB[k], s1);
            }
        }
    }
    const int ob = ((b * DEL + j0 + 2 * half) * EDIM) + t;
    out[ob       ] = de[ob       ] + s0;
    out[ob + EDIM] = de[ob + EDIM] + s1;
}

// ---------------------------------------------------------------------------
extern "C" void kernel_launch(void* const* d_in, const int* in_sizes, int n_in,
                              void* d_out, int out_size)
{
    const float* en     = (const float*)d_in[0];
    const float* de     = (const float*)d_in[1];
    const float* topics = (const float*)d_in[2];
    const float* w_en   = (const float*)d_in[3];
    const float* w_de   = (const float*)d_in[4];
    const float* nu     = (const float*)d_in[5];
    const float* wt     = (const float*)d_in[6];
    float* out = (float*)d_out;

    k_gemm_aeT<<<dim3(ENL / 64, UDIM / 128, BSZ), 256>>>(en, w_en);
    k_c<<<dim3(UDIM / 64, BSZ), 256>>>(de, w_de, topics, wt);
    k_attn<<<dim3(DEL / 4, BSZ), 1024>>>(en, de, nu, out);
}